// round 2
// baseline (speedup 1.0000x reference)
#include <cuda_runtime.h>
#include <math.h>

// ---------------------------------------------------------------------------
// MoE top-2-of-8, fp32. Sparse grouped-GEMM formulation of the dense reference.
//  1) init: zero out + pair scratch
//  2) gate: logits, top-2, softmax  -> per-token (e0,e1,p0,p1)
//  3) offsets: per-expert counts -> 128-padded segment offsets
//  4) assign: deterministic ordered compaction into pair arrays
//  5) pass1: h = gelu(x_gathered @ w1[e]^T + b1[e])   -> g_h  (fp32)
//  6) pass2: out += p * (h @ w2[e]^T + b2[e])         (atomicAdd, 2 adds/elem)
// R1 fix: __align__(16) on shared tiles (float4 reinterpret trap).
// ---------------------------------------------------------------------------

#define BATCH 8192
#define NEXP  8
#define DIN   2048
#define DHID  8192
#define DOUT  2048

#define BM 128
#define BN 128
#define BK 16
#define TM 8
#define TN 8
#define NTHREADS 256

#define MAX_ROWS 17408            // 16384 pairs + 8 experts * 128 padding
#define NMT (MAX_ROWS / BM)       // 136 max M-tiles

// ---- device scratch (static globals; no allocation in kernel_launch) ------
__device__ float g_h[(size_t)MAX_ROWS * DHID];   // ~544 MB intermediate
__device__ int   g_tok_e[BATCH * 2];
__device__ float g_tok_p[BATCH * 2];
__device__ int   g_pair_token[MAX_ROWS];
__device__ float g_pair_w[MAX_ROWS];
__device__ int   g_offsets[NEXP + 1];

// ---------------------------------------------------------------------------
__global__ void init_kernel(float* __restrict__ out, int out_n) {
    int stride = gridDim.x * blockDim.x;
    int i0 = blockIdx.x * blockDim.x + threadIdx.x;
    for (int i = i0; i < out_n; i += stride) out[i] = 0.0f;
    for (int i = i0; i < MAX_ROWS; i += stride) {
        g_pair_token[i] = 0;
        g_pair_w[i] = 0.0f;
    }
}

// ---------------------------------------------------------------------------
// Router: one warp per token.
__global__ void gate_kernel(const float* __restrict__ x,
                            const float* __restrict__ gw) {
    int gtid = blockIdx.x * blockDim.x + threadIdx.x;
    int t = gtid >> 5;
    int lane = gtid & 31;
    if (t >= BATCH) return;
    const float* xr = x + (size_t)t * DIN;

    float acc[NEXP];
#pragma unroll
    for (int e = 0; e < NEXP; e++) acc[e] = 0.0f;

    for (int k = lane; k < DIN; k += 32) {
        float xv = __ldg(xr + k);
#pragma unroll
        for (int e = 0; e < NEXP; e++) acc[e] += xv * __ldg(gw + e * DIN + k);
    }
#pragma unroll
    for (int off = 16; off > 0; off >>= 1) {
#pragma unroll
        for (int e = 0; e < NEXP; e++)
            acc[e] += __shfl_xor_sync(0xffffffffu, acc[e], off);
    }
    if (lane == 0) {
        float v0 = -1e30f, v1 = -1e30f;
        int i0 = 0, i1 = 0;
#pragma unroll
        for (int e = 0; e < NEXP; e++) {
            float v = acc[e];
            if (v > v0) { v1 = v0; i1 = i0; v0 = v; i0 = e; }
            else if (v > v1) { v1 = v; i1 = e; }
        }
        float e1 = expf(v1 - v0);
        float s = 1.0f + e1;
        g_tok_e[2 * t + 0] = i0;
        g_tok_e[2 * t + 1] = i1;
        g_tok_p[2 * t + 0] = 1.0f / s;
        g_tok_p[2 * t + 1] = e1 / s;
    }
}

// ---------------------------------------------------------------------------
// Counts -> 128-padded exclusive segment offsets. 1 block.
__global__ void offsets_kernel() {
    __shared__ int cnt[NEXP];
    if (threadIdx.x < NEXP) cnt[threadIdx.x] = 0;
    __syncthreads();
    for (int t = threadIdx.x; t < BATCH; t += blockDim.x) {
        atomicAdd(&cnt[g_tok_e[2 * t + 0]], 1);
        atomicAdd(&cnt[g_tok_e[2 * t + 1]], 1);
    }
    __syncthreads();
    if (threadIdx.x == 0) {
        int off = 0;
        for (int e = 0; e < NEXP; e++) {
            g_offsets[e] = off;
            off += ((cnt[e] + BM - 1) / BM) * BM;
        }
        g_offsets[NEXP] = off;
    }
}

// ---------------------------------------------------------------------------
// Deterministic ordered compaction: block e fills its expert segment in
// token order (ballot scan). No global atomics -> stable slot assignment.
__global__ void assign_kernel() {
    int e = blockIdx.x;
    __shared__ int wcnt[8];
    __shared__ int sbase;
    if (threadIdx.x == 0) sbase = g_offsets[e];
    __syncthreads();
    int base = sbase;
    int lane = threadIdx.x & 31;
    int wid = threadIdx.x >> 5;
    for (int t0 = 0; t0 < BATCH; t0 += 256) {
        int t = t0 + threadIdx.x;
        int sel = 0;
        float w = 0.0f;
        int e0 = g_tok_e[2 * t], e1 = g_tok_e[2 * t + 1];
        if (e0 == e)      { sel = 1; w = g_tok_p[2 * t]; }
        else if (e1 == e) { sel = 1; w = g_tok_p[2 * t + 1]; }
        unsigned m = __ballot_sync(0xffffffffu, sel);
        if (lane == 0) wcnt[wid] = __popc(m);
        __syncthreads();
        int prefix = 0, tot = 0;
#pragma unroll
        for (int i = 0; i < 8; i++) {
            if (i < wid) prefix += wcnt[i];
            tot += wcnt[i];
        }
        if (sel) {
            int pos = base + prefix + __popc(m & ((1u << lane) - 1u));
            g_pair_token[pos] = t;
            g_pair_w[pos] = w;
        }
        base += tot;
        __syncthreads();
    }
}

// ---------------------------------------------------------------------------
// Pass 1: h[slot, :] = gelu(x[token] @ w1[e]^T + b1[e]).
// Grid: (mt fast, nt) so x (64MB) stays L2-resident; w1 streams once.
__global__ __launch_bounds__(NTHREADS, 2)
void pass1_kernel(const float* __restrict__ x,
                  const float* __restrict__ w1,
                  const float* __restrict__ b1) {
    const int mt = blockIdx.x;
    const int nt = blockIdx.y;
    __shared__ __align__(16) float As[BK][BM + 4];
    __shared__ __align__(16) float Bs[BK][BN + 4];
    __shared__ int s_off[NEXP + 1];
    __shared__ int stok[BM];

    const int tid = threadIdx.x;
    if (tid < NEXP + 1) s_off[tid] = g_offsets[tid];
    __syncthreads();
    const int row0 = mt * BM;
    if (row0 >= s_off[NEXP]) return;
    int e = 0;
    while (row0 >= s_off[e + 1]) e++;

    if (tid < BM) stok[tid] = g_pair_token[row0 + tid];
    __syncthreads();

    const int r = tid >> 2;
    const int c = (tid & 3) * 4;
    const float* a0 = x + (size_t)stok[r] * DIN + c;
    const float* a1 = x + (size_t)stok[r + 64] * DIN + c;
    const float* wB = w1 + (size_t)e * DHID * DIN + (size_t)(nt * BN) * DIN;
    const float* bb0 = wB + (size_t)r * DIN + c;
    const float* bb1 = wB + (size_t)(r + 64) * DIN + c;

    float acc[TM][TN];
#pragma unroll
    for (int i = 0; i < TM; i++)
#pragma unroll
        for (int j = 0; j < TN; j++) acc[i][j] = 0.0f;

    const int tx = tid & 15;
    const int ty = tid >> 4;

    for (int k0 = 0; k0 < DIN; k0 += BK) {
        float4 va0 = *(const float4*)(a0 + k0);
        float4 va1 = *(const float4*)(a1 + k0);
        float4 vb0 = *(const float4*)(bb0 + k0);
        float4 vb1 = *(const float4*)(bb1 + k0);
        __syncthreads();
        As[c + 0][r] = va0.x; As[c + 1][r] = va0.y; As[c + 2][r] = va0.z; As[c + 3][r] = va0.w;
        As[c + 0][r + 64] = va1.x; As[c + 1][r + 64] = va1.y; As[c + 2][r + 64] = va1.z; As[c + 3][r + 64] = va1.w;
        Bs[c + 0][r] = vb0.x; Bs[c + 1][r] = vb0.y; Bs[c + 2][r] = vb0.z; Bs[c + 3][r] = vb0.w;
        Bs[c + 0][r + 64] = vb1.x; Bs[c + 1][r + 64] = vb1.y; Bs[c + 2][r + 64] = vb1.z; Bs[c + 3][r + 64] = vb1.w;
        __syncthreads();
#pragma unroll
        for (int kk = 0; kk < BK; kk++) {
            float a[TM], b[TN];
            float4 ta0 = *(const float4*)&As[kk][ty * TM];
            float4 ta1 = *(const float4*)&As[kk][ty * TM + 4];
            float4 tb0 = *(const float4*)&Bs[kk][tx * TN];
            float4 tb1 = *(const float4*)&Bs[kk][tx * TN + 4];
            a[0] = ta0.x; a[1] = ta0.y; a[2] = ta0.z; a[3] = ta0.w;
            a[4] = ta1.x; a[5] = ta1.y; a[6] = ta1.z; a[7] = ta1.w;
            b[0] = tb0.x; b[1] = tb0.y; b[2] = tb0.z; b[3] = tb0.w;
            b[4] = tb1.x; b[5] = tb1.y; b[6] = tb1.z; b[7] = tb1.w;
#pragma unroll
            for (int i = 0; i < TM; i++)
#pragma unroll
                for (int j = 0; j < TN; j++) acc[i][j] += a[i] * b[j];
        }
    }

    const int ncol = nt * BN + tx * TN;
    float bv[TN];
#pragma unroll
    for (int j = 0; j < TN; j++) bv[j] = b1[(size_t)e * DHID + ncol + j];
#pragma unroll
    for (int i = 0; i < TM; i++) {
        size_t slot = (size_t)(row0 + ty * TM + i);
        float o[TN];
#pragma unroll
        for (int j = 0; j < TN; j++) {
            float v = acc[i][j] + bv[j];
            o[j] = 0.5f * v * (1.0f + erff(v * 0.7071067811865476f));
        }
        float* dst = g_h + slot * DHID + ncol;
        *(float4*)(dst) = make_float4(o[0], o[1], o[2], o[3]);
        *(float4*)(dst + 4) = make_float4(o[4], o[5], o[6], o[7]);
    }
}

// ---------------------------------------------------------------------------
// Pass 2: out[token] += p * (h[slot] @ w2[e]^T + b2[e]).
// Grid: (nt fast, mt) so w2[e] (64MB) stays L2-resident; h streams once.
__global__ __launch_bounds__(NTHREADS, 2)
void pass2_kernel(const float* __restrict__ w2,
                  const float* __restrict__ b2,
                  float* __restrict__ out) {
    const int nt = blockIdx.x;
    const int mt = blockIdx.y;
    __shared__ __align__(16) float As[BK][BM + 4];
    __shared__ __align__(16) float Bs[BK][BN + 4];
    __shared__ int s_off[NEXP + 1];
    __shared__ int stok[BM];
    __shared__ float ssw[BM];

    const int tid = threadIdx.x;
    if (tid < NEXP + 1) s_off[tid] = g_offsets[tid];
    __syncthreads();
    const int row0 = mt * BM;
    if (row0 >= s_off[NEXP]) return;
    int e = 0;
    while (row0 >= s_off[e + 1]) e++;

    if (tid < BM) {
        stok[tid] = g_pair_token[row0 + tid];
        ssw[tid] = g_pair_w[row0 + tid];
    }
    __syncthreads();

    const int r = tid >> 2;
    const int c = (tid & 3) * 4;
    const float* a0 = g_h + (size_t)(row0 + r) * DHID + c;
    const float* a1 = g_h + (size_t)(row0 + r + 64) * DHID + c;
    const float* wB = w2 + (size_t)e * DOUT * DHID + (size_t)(nt * BN) * DHID;
    const float* bb0 = wB + (size_t)r * DHID + c;
    const float* bb1 = wB + (size_t)(r + 64) * DHID + c;

    float acc[TM][TN];
#pragma unroll
    for (int i = 0; i < TM; i++)
#pragma unroll
        for (int j = 0; j < TN; j++) acc[i][j] = 0.0f;

    const int tx = tid & 15;
    const int ty = tid >> 4;

    for (int k0 = 0; k0 < DHID; k0 += BK) {
        float4 va0 = *(const float4*)(a0 + k0);
        float4 va1 = *(const float4*)(a1 + k0);
        float4 vb0 = *(const float4*)(bb0 + k0);
        float4 vb1 = *(const float4*)(bb1 + k0);
        __syncthreads();
        As[c + 0][r] = va0.x; As[c + 1][r] = va0.y; As[c + 2][r] = va0.z; As[c + 3][r] = va0.w;
        As[c + 0][r + 64] = va1.x; As[c + 1][r + 64] = va1.y; As[c + 2][r + 64] = va1.z; As[c + 3][r + 64] = va1.w;
        Bs[c + 0][r] = vb0.x; Bs[c + 1][r] = vb0.y; Bs[c + 2][r] = vb0.z; Bs[c + 3][r] = vb0.w;
        Bs[c + 0][r + 64] = vb1.x; Bs[c + 1][r + 64] = vb1.y; Bs[c + 2][r + 64] = vb1.z; Bs[c + 3][r + 64] = vb1.w;
        __syncthreads();
#pragma unroll
        for (int kk = 0; kk < BK; kk++) {
            float a[TM], b[TN];
            float4 ta0 = *(const float4*)&As[kk][ty * TM];
            float4 ta1 = *(const float4*)&As[kk][ty * TM + 4];
            float4 tb0 = *(const float4*)&Bs[kk][tx * TN];
            float4 tb1 = *(const float4*)&Bs[kk][tx * TN + 4];
            a[0] = ta0.x; a[1] = ta0.y; a[2] = ta0.z; a[3] = ta0.w;
            a[4] = ta1.x; a[5] = ta1.y; a[6] = ta1.z; a[7] = ta1.w;
            b[0] = tb0.x; b[1] = tb0.y; b[2] = tb0.z; b[3] = tb0.w;
            b[4] = tb1.x; b[5] = tb1.y; b[6] = tb1.z; b[7] = tb1.w;
#pragma unroll
            for (int i = 0; i < TM; i++)
#pragma unroll
                for (int j = 0; j < TN; j++) acc[i][j] += a[i] * b[j];
        }
    }

    const int ncol = nt * BN + tx * TN;
    float bv[TN];
#pragma unroll
    for (int j = 0; j < TN; j++) bv[j] = b2[(size_t)e * DOUT + ncol + j];
#pragma unroll
    for (int i = 0; i < TM; i++) {
        int lrow = ty * TM + i;
        int tok = stok[lrow];
        float w = ssw[lrow];
        float* orow = out + (size_t)tok * DOUT + ncol;
#pragma unroll
        for (int j = 0; j < TN; j++)
            atomicAdd(orow + j, w * (acc[i][j] + bv[j]));
    }
}

// ---------------------------------------------------------------------------
extern "C" void kernel_launch(void* const* d_in, const int* in_sizes, int n_in,
                              void* d_out, int out_size) {
    const float* x    = (const float*)d_in[0];
    const float* gw   = (const float*)d_in[1];
    const float* w1   = (const float*)d_in[2];
    const float* b1   = (const float*)d_in[3];
    const float* w2   = (const float*)d_in[4];
    const float* b2   = (const float*)d_in[5];
    float* out = (float*)d_out;

    init_kernel<<<2048, 256>>>(out, out_size);
    gate_kernel<<<(BATCH * 32 + 255) / 256, 256>>>(x, gw);
    offsets_kernel<<<1, 256>>>();
    assign_kernel<<<NEXP, 256>>>();
    pass1_kernel<<<dim3(NMT, DHID / BN), NTHREADS>>>(x, w1, b1);
    pass2_kernel<<<dim3(DOUT / BN, NMT), NTHREADS>>>(w2, b2, out);
}

// round 4
// speedup vs baseline: 2.5480x; 2.5480x over previous
#include <cuda_runtime.h>
#include <cuda_bf16.h>
#include <math.h>
#include <stdint.h>

// ---------------------------------------------------------------------------
// MoE top-2-of-8 via mma.sync bf16 HMMA (bf16x3 split emulating fp32).
// tcgen05 unavailable: harness PTX target is compute_103 (no 'a' features).
//  - split: w1,w2,x -> bf16 (hi=trunc, lo=rn residual) arrays in gmem
//  - pass1: h = gelu(x @ w1[e]^T + b1[e]) -> h_hi/h_lo bf16
//  - pass2: out += p * (h @ w2[e]^T + b2[e])  (fp32 atomicAdd)
// GEMM: 128x128 tiles, K-chunks of 64, cp.async 3-stage, ldmatrix + HMMA.
// 3 products per frag: hi*hi + hi*lo + lo*hi (residual ~2^-16).
// ---------------------------------------------------------------------------

#define BATCH 8192
#define NEXP  8
#define DIN   2048
#define DHID  8192
#define DOUT  2048

#define BM 128
#define BN 128
#define MAX_ROWS 17408
#define NMT (MAX_ROWS / BM)

#define STAGE_B 65536
#define AH_O 0
#define AL_O 16384
#define BH_O 32768
#define BL_O 49152
#define DYN_BYTES (3 * STAGE_B + 1024)

#define SWZ(o) ((o) ^ (((o) >> 3) & 0x70))

// ---- device scratch --------------------------------------------------------
__device__ __nv_bfloat16 g_w1h[(size_t)NEXP * DHID * DIN];
__device__ __nv_bfloat16 g_w1l[(size_t)NEXP * DHID * DIN];
__device__ __nv_bfloat16 g_w2h[(size_t)NEXP * DOUT * DHID];
__device__ __nv_bfloat16 g_w2l[(size_t)NEXP * DOUT * DHID];
__device__ __nv_bfloat16 g_xh[(size_t)BATCH * DIN];
__device__ __nv_bfloat16 g_xl[(size_t)BATCH * DIN];
__device__ __nv_bfloat16 g_hh[(size_t)MAX_ROWS * DHID];
__device__ __nv_bfloat16 g_hl[(size_t)MAX_ROWS * DHID];

__device__ int   g_tok_e[BATCH * 2];
__device__ float g_tok_p[BATCH * 2];
__device__ int   g_pair_token[MAX_ROWS];
__device__ float g_pair_w[MAX_ROWS];
__device__ int   g_offsets[NEXP + 1];

// ---- helpers ----------------------------------------------------------------
__device__ __forceinline__ uint32_t smem_u32(const void* p) {
    uint32_t a;
    asm("{ .reg .u64 t; cvta.to.shared.u64 t, %1; cvt.u32.u64 %0, t; }"
        : "=r"(a) : "l"(p));
    return a;
}
__device__ __forceinline__ void cp16(uint32_t s, const void* g) {
    asm volatile("cp.async.cg.shared.global [%0], [%1], 16;" :: "r"(s), "l"(g));
}
__device__ __forceinline__ void cp_commit() {
    asm volatile("cp.async.commit_group;" ::: "memory");
}
template <int N>
__device__ __forceinline__ void cp_wait() {
    asm volatile("cp.async.wait_group %0;" :: "n"(N) : "memory");
}
__device__ __forceinline__ void ldsm4(uint32_t* r, uint32_t addr) {
    asm volatile("ldmatrix.sync.aligned.m8n8.x4.shared.b16 {%0,%1,%2,%3}, [%4];"
                 : "=r"(r[0]), "=r"(r[1]), "=r"(r[2]), "=r"(r[3]) : "r"(addr));
}
__device__ __forceinline__ void mma16816(float* d, const uint32_t* a,
                                         const uint32_t* b) {
    asm volatile(
        "mma.sync.aligned.m16n8k16.row.col.f32.bf16.bf16.f32 "
        "{%0,%1,%2,%3}, {%4,%5,%6,%7}, {%8,%9}, {%0,%1,%2,%3};"
        : "+f"(d[0]), "+f"(d[1]), "+f"(d[2]), "+f"(d[3])
        : "r"(a[0]), "r"(a[1]), "r"(a[2]), "r"(a[3]), "r"(b[0]), "r"(b[1]));
}
__device__ __forceinline__ void split4(float4 v, uint32_t& hi0, uint32_t& hi1,
                                       uint32_t& lo0, uint32_t& lo1) {
    uint32_t ux = __float_as_uint(v.x), uy = __float_as_uint(v.y);
    uint32_t uz = __float_as_uint(v.z), uw = __float_as_uint(v.w);
    hi0 = __byte_perm(ux, uy, 0x7632);
    hi1 = __byte_perm(uz, uw, 0x7632);
    float lx = v.x - __uint_as_float(ux & 0xFFFF0000u);
    float ly = v.y - __uint_as_float(uy & 0xFFFF0000u);
    float lz = v.z - __uint_as_float(uz & 0xFFFF0000u);
    float lw = v.w - __uint_as_float(uw & 0xFFFF0000u);
    __nv_bfloat162 l0 = __floats2bfloat162_rn(lx, ly);
    __nv_bfloat162 l1 = __floats2bfloat162_rn(lz, lw);
    lo0 = *(uint32_t*)&l0;
    lo1 = *(uint32_t*)&l1;
}
__device__ __forceinline__ float geluf(float v) {
    return 0.5f * v * (1.0f + erff(v * 0.7071067811865476f));
}
__device__ __forceinline__ void store_split(__nv_bfloat16* hh, __nv_bfloat16* hl,
                                            size_t off, float v0, float v1) {
    uint32_t u0 = __float_as_uint(v0), u1 = __float_as_uint(v1);
    uint32_t hi = __byte_perm(u0, u1, 0x7632);
    float l0 = v0 - __uint_as_float(u0 & 0xFFFF0000u);
    float l1 = v1 - __uint_as_float(u1 & 0xFFFF0000u);
    __nv_bfloat162 lp = __floats2bfloat162_rn(l0, l1);
    *(uint32_t*)(hh + off) = hi;
    *(uint32_t*)(hl + off) = *(uint32_t*)&lp;
}

// ---------------------------------------------------------------------------
__global__ void init_kernel(float* __restrict__ out, int out_n) {
    int stride = gridDim.x * blockDim.x;
    int i0 = blockIdx.x * blockDim.x + threadIdx.x;
    for (int i = i0; i < out_n; i += stride) out[i] = 0.0f;
    for (int i = i0; i < MAX_ROWS; i += stride) {
        g_pair_token[i] = 0;
        g_pair_w[i] = 0.0f;
    }
}

__global__ void gate_kernel(const float* __restrict__ x,
                            const float* __restrict__ gw) {
    int gtid = blockIdx.x * blockDim.x + threadIdx.x;
    int t = gtid >> 5;
    int lane = gtid & 31;
    if (t >= BATCH) return;
    const float* xr = x + (size_t)t * DIN;
    float acc[NEXP];
#pragma unroll
    for (int e = 0; e < NEXP; e++) acc[e] = 0.0f;
    for (int k = lane; k < DIN; k += 32) {
        float xv = __ldg(xr + k);
#pragma unroll
        for (int e = 0; e < NEXP; e++) acc[e] += xv * __ldg(gw + e * DIN + k);
    }
#pragma unroll
    for (int off = 16; off > 0; off >>= 1) {
#pragma unroll
        for (int e = 0; e < NEXP; e++)
            acc[e] += __shfl_xor_sync(0xffffffffu, acc[e], off);
    }
    if (lane == 0) {
        float v0 = -1e30f, v1 = -1e30f;
        int i0 = 0, i1 = 0;
#pragma unroll
        for (int e = 0; e < NEXP; e++) {
            float v = acc[e];
            if (v > v0) { v1 = v0; i1 = i0; v0 = v; i0 = e; }
            else if (v > v1) { v1 = v; i1 = e; }
        }
        float e1 = expf(v1 - v0);
        float s = 1.0f + e1;
        g_tok_e[2 * t + 0] = i0;
        g_tok_e[2 * t + 1] = i1;
        g_tok_p[2 * t + 0] = 1.0f / s;
        g_tok_p[2 * t + 1] = e1 / s;
    }
}

__global__ void offsets_kernel() {
    __shared__ int cnt[NEXP];
    if (threadIdx.x < NEXP) cnt[threadIdx.x] = 0;
    __syncthreads();
    for (int t = threadIdx.x; t < BATCH; t += blockDim.x) {
        atomicAdd(&cnt[g_tok_e[2 * t + 0]], 1);
        atomicAdd(&cnt[g_tok_e[2 * t + 1]], 1);
    }
    __syncthreads();
    if (threadIdx.x == 0) {
        int off = 0;
        for (int e = 0; e < NEXP; e++) {
            g_offsets[e] = off;
            off += ((cnt[e] + BM - 1) / BM) * BM;
        }
        g_offsets[NEXP] = off;
    }
}

__global__ void assign_kernel() {
    int e = blockIdx.x;
    __shared__ int wcnt[8];
    __shared__ int sbase;
    if (threadIdx.x == 0) sbase = g_offsets[e];
    __syncthreads();
    int base = sbase;
    int lane = threadIdx.x & 31;
    int wid = threadIdx.x >> 5;
    for (int t0 = 0; t0 < BATCH; t0 += 256) {
        int t = t0 + threadIdx.x;
        int sel = 0;
        float w = 0.0f;
        int e0 = g_tok_e[2 * t], e1 = g_tok_e[2 * t + 1];
        if (e0 == e)      { sel = 1; w = g_tok_p[2 * t]; }
        else if (e1 == e) { sel = 1; w = g_tok_p[2 * t + 1]; }
        unsigned m = __ballot_sync(0xffffffffu, sel);
        if (lane == 0) wcnt[wid] = __popc(m);
        __syncthreads();
        int prefix = 0, tot = 0;
#pragma unroll
        for (int i = 0; i < 8; i++) {
            if (i < wid) prefix += wcnt[i];
            tot += wcnt[i];
        }
        if (sel) {
            int pos = base + prefix + __popc(m & ((1u << lane) - 1u));
            g_pair_token[pos] = t;
            g_pair_w[pos] = w;
        }
        base += tot;
        __syncthreads();
    }
}

// fp32 -> bf16 hi/lo split into device globals (which: 0=w1, 1=w2, 2=x)
__global__ void split_sel(const float4* __restrict__ src, size_t n4, int which) {
    uint2* hi;
    uint2* lo;
    if (which == 0)      { hi = (uint2*)g_w1h; lo = (uint2*)g_w1l; }
    else if (which == 1) { hi = (uint2*)g_w2h; lo = (uint2*)g_w2l; }
    else                 { hi = (uint2*)g_xh;  lo = (uint2*)g_xl;  }
    size_t i = (size_t)blockIdx.x * blockDim.x + threadIdx.x;
    size_t stride = (size_t)gridDim.x * blockDim.x;
    for (; i < n4; i += stride) {
        float4 v = src[i];
        uint32_t h0, h1, l0, l1;
        split4(v, h0, h1, l0, l1);
        hi[i] = make_uint2(h0, h1);
        lo[i] = make_uint2(l0, l1);
    }
}

// ---------------------------------------------------------------------------
// Grouped GEMM: C[128x128] = A[128xK] * B[128xK]^T via bf16x3 HMMA.
// P1: A = x split (token gather), B = w1 split, epilogue gelu -> h split.
// P2: A = h split (direct rows),  B = w2 split, epilogue atomicAdd out.
// ---------------------------------------------------------------------------
template <int KDIM, bool P1>
__global__ void __launch_bounds__(256, 1)
mma_gemm(const float* __restrict__ bias, float* __restrict__ out) {
    const int mt = P1 ? blockIdx.x : blockIdx.y;
    const int nt = P1 ? blockIdx.y : blockIdx.x;
    __shared__ int s_off[NEXP + 1];
    __shared__ int stok[BM];
    __shared__ float ssw[BM];
    __shared__ float sbias[BN];
    extern __shared__ char dsm[];

    const int tid = threadIdx.x;
    if (tid < NEXP + 1) s_off[tid] = g_offsets[tid];
    __syncthreads();
    const int row0 = mt * BM;
    if (row0 >= s_off[NEXP]) return;
    int e = 0;
    while (row0 >= s_off[e + 1]) e++;
    if (tid < BM) {
        stok[tid] = g_pair_token[row0 + tid];
        ssw[tid] = g_pair_w[row0 + tid];
    }
    if (tid < BN)
        sbias[tid] = bias[(size_t)e * (P1 ? DHID : DOUT) + (size_t)nt * BN + tid];
    __syncthreads();

    const __nv_bfloat16* Agh = P1 ? g_xh : g_hh;
    const __nv_bfloat16* Agl = P1 ? g_xl : g_hl;
    const __nv_bfloat16* Bgh = P1 ? g_w1h : g_w2h;
    const __nv_bfloat16* Bgl = P1 ? g_w1l : g_w2l;

    uintptr_t pal = ((uintptr_t)dsm + 1023) & ~(uintptr_t)1023;
    const uint32_t su = smem_u32((void*)pal);

    // ---- cp.async producer mapping: thread -> 4 rows x 1 chunk per array ----
    const int ch = tid & 7;
    const int rb = tid >> 3;
    const __nv_bfloat16* aH[4];
    const __nv_bfloat16* aL[4];
    const __nv_bfloat16* bH[4];
    const __nv_bfloat16* bL[4];
    uint32_t swz[4];
    const size_t brow0 = (size_t)e * (P1 ? DHID : DOUT) + (size_t)nt * BN;
#pragma unroll
    for (int i = 0; i < 4; i++) {
        int r = rb + i * 32;
        size_t ga = P1 ? (size_t)stok[r] * KDIM : (size_t)(row0 + r) * KDIM;
        aH[i] = Agh + ga + ch * 8;
        aL[i] = Agl + ga + ch * 8;
        size_t gb = (brow0 + r) * (size_t)KDIM;
        bH[i] = Bgh + gb + ch * 8;
        bL[i] = Bgl + gb + ch * 8;
        swz[i] = SWZ((uint32_t)r * 128 + (uint32_t)ch * 16);
    }

    auto issue = [&](int kt, int st) {
        uint32_t sb = su + st * STAGE_B;
        int ko = kt * 64;
#pragma unroll
        for (int i = 0; i < 4; i++) {
            cp16(sb + AH_O + swz[i], aH[i] + ko);
            cp16(sb + AL_O + swz[i], aL[i] + ko);
            cp16(sb + BH_O + swz[i], bH[i] + ko);
            cp16(sb + BL_O + swz[i], bL[i] + ko);
        }
    };

    issue(0, 0);
    cp_commit();
    issue(1, 1);
    cp_commit();

    // ---- consumer mapping ----
    const int wid = tid >> 5, lane = tid & 31;
    const int warp_m = (wid >> 1) * 32;
    const int warp_n = (wid & 1) * 64;
    const uint32_t xorv = (uint32_t)(lane & 7) << 4;
    const uint32_t kx = (uint32_t)((lane >> 4) << 4);
    const uint32_t rowA =
        (uint32_t)(warp_m + (lane & 7) + ((lane >> 3) & 1) * 8) * 128;
    const uint32_t rowB =
        (uint32_t)(warp_n + (lane & 7) + ((lane >> 3) & 1) * 8) * 128;

    float acc[2][8][4];
#pragma unroll
    for (int i = 0; i < 2; i++)
#pragma unroll
        for (int j = 0; j < 8; j++)
#pragma unroll
            for (int q = 0; q < 4; q++) acc[i][j][q] = 0.0f;

    const int NCH = KDIM / 64;
#pragma unroll 1
    for (int c = 0; c < NCH; c++) {
        cp_wait<1>();
        __syncthreads();
        if (c + 2 < NCH) issue(c + 2, (c + 2) % 3);
        cp_commit();
        const uint32_t sb = su + (c % 3) * STAGE_B;
#pragma unroll
        for (int s = 0; s < 4; s++) {
            const uint32_t kt = (((uint32_t)(s * 32)) + kx) ^ xorv;
            uint32_t ah[2][4], al[2][4], bh[4][4], bl[4][4];
            ldsm4(ah[0], sb + AH_O + rowA + kt);
            ldsm4(ah[1], sb + AH_O + rowA + 2048 + kt);
            ldsm4(al[0], sb + AL_O + rowA + kt);
            ldsm4(al[1], sb + AL_O + rowA + 2048 + kt);
#pragma unroll
            for (int j = 0; j < 4; j++) {
                ldsm4(bh[j], sb + BH_O + rowB + j * 2048 + kt);
                ldsm4(bl[j], sb + BL_O + rowB + j * 2048 + kt);
            }
#pragma unroll
            for (int mi = 0; mi < 2; mi++)
#pragma unroll
                for (int nj = 0; nj < 8; nj++) {
                    uint32_t bhi[2] = {bh[nj >> 1][nj & 1], bh[nj >> 1][(nj & 1) + 2]};
                    uint32_t blo[2] = {bl[nj >> 1][nj & 1], bl[nj >> 1][(nj & 1) + 2]};
                    mma16816(acc[mi][nj], ah[mi], bhi);
                    mma16816(acc[mi][nj], ah[mi], blo);
                    mma16816(acc[mi][nj], al[mi], bhi);
                }
        }
    }

    // ---- epilogue ----
    const int g = lane >> 2, t4 = lane & 3;
    if (P1) {
#pragma unroll
        for (int mi = 0; mi < 2; mi++) {
            int r0 = warp_m + mi * 16 + g;
#pragma unroll
            for (int nj = 0; nj < 8; nj++) {
                int cB = warp_n + nj * 8 + 2 * t4;
                float b0v = sbias[cB], b1v = sbias[cB + 1];
                float v00 = geluf(acc[mi][nj][0] + b0v);
                float v01 = geluf(acc[mi][nj][1] + b1v);
                float v10 = geluf(acc[mi][nj][2] + b0v);
                float v11 = geluf(acc[mi][nj][3] + b1v);
                size_t gc = (size_t)nt * BN + cB;
                store_split(g_hh, g_hl, (size_t)(row0 + r0) * DHID + gc, v00, v01);
                store_split(g_hh, g_hl, (size_t)(row0 + r0 + 8) * DHID + gc, v10, v11);
            }
        }
    } else {
#pragma unroll
        for (int mi = 0; mi < 2; mi++) {
            int r0 = warp_m + mi * 16 + g;
            int tok0 = stok[r0], tok1 = stok[r0 + 8];
            float w0 = ssw[r0], w1 = ssw[r0 + 8];
            float* o0 = out + (size_t)tok0 * DOUT + (size_t)nt * BN;
            float* o1 = out + (size_t)tok1 * DOUT + (size_t)nt * BN;
#pragma unroll
            for (int nj = 0; nj < 8; nj++) {
                int cB = warp_n + nj * 8 + 2 * t4;
                float b0v = sbias[cB], b1v = sbias[cB + 1];
                atomicAdd(o0 + cB,     w0 * (acc[mi][nj][0] + b0v));
                atomicAdd(o0 + cB + 1, w0 * (acc[mi][nj][1] + b1v));
                atomicAdd(o1 + cB,     w1 * (acc[mi][nj][2] + b0v));
                atomicAdd(o1 + cB + 1, w1 * (acc[mi][nj][3] + b1v));
            }
        }
    }
}

// ---------------------------------------------------------------------------
extern "C" void kernel_launch(void* const* d_in, const int* in_sizes, int n_in,
                              void* d_out, int out_size) {
    const float* x  = (const float*)d_in[0];
    const float* gw = (const float*)d_in[1];
    const float* w1 = (const float*)d_in[2];
    const float* b1 = (const float*)d_in[3];
    const float* w2 = (const float*)d_in[4];
    const float* b2 = (const float*)d_in[5];
    float* out = (float*)d_out;

    cudaFuncSetAttribute(mma_gemm<DIN, true>,
                         cudaFuncAttributeMaxDynamicSharedMemorySize, DYN_BYTES);
    cudaFuncSetAttribute(mma_gemm<DHID, false>,
                         cudaFuncAttributeMaxDynamicSharedMemorySize, DYN_BYTES);

    init_kernel<<<2048, 256>>>(out, out_size);
    gate_kernel<<<(BATCH * 32 + 255) / 256, 256>>>(x, gw);
    offsets_kernel<<<1, 256>>>();
    assign_kernel<<<NEXP, 256>>>();

    size_t n4x = (size_t)BATCH * DIN / 4;
    size_t n4w1 = (size_t)NEXP * DHID * DIN / 4;
    size_t n4w2 = (size_t)NEXP * DOUT * DHID / 4;
    split_sel<<<(int)((n4x + 255) / 256), 256>>>((const float4*)x, n4x, 2);
    split_sel<<<65536, 256>>>((const float4*)w1, n4w1, 0);
    split_sel<<<65536, 256>>>((const float4*)w2, n4w2, 1);

    mma_gemm<DIN, true><<<dim3(NMT, DHID / BN), 256, DYN_BYTES>>>(b1, nullptr);
    mma_gemm<DHID, false><<<dim3(DOUT / BN, NMT), 256, DYN_BYTES>>>(b2, out);
}

// round 5
// speedup vs baseline: 3.5680x; 1.4003x over previous
#include <cuda_runtime.h>
#include <cuda_fp16.h>
#include <math.h>
#include <stdint.h>

// ---------------------------------------------------------------------------
// MoE top-2-of-8 via mma.sync fp16 HMMA, asymmetric fp16x2 split:
//   A side (x, h) split: a = ah + al  (both fp16 rn; exact to ~2^-24)
//   B side (w1, w2) rounded once: bh = fp16(b)   (error ~2^-12, incoherent)
//   d = ah*bh + al*bh  -> 2 MMAs per element (was 3 with bf16x3).
//  - pass1: h = gelu(x @ w1[e]^T + b1[e]) -> h_hi/h_lo fp16
//  - pass2: out += p * (h @ w2[e]^T + b2[e])  (fp32 atomicAdd)
// GEMM: 128x128 tiles, K-chunks of 64, cp.async 3-stage, ldmatrix + HMMA.
// ---------------------------------------------------------------------------

#define BATCH 8192
#define NEXP  8
#define DIN   2048
#define DHID  8192
#define DOUT  2048

#define BM 128
#define BN 128
#define MAX_ROWS 17408
#define NMT (MAX_ROWS / BM)

#define STAGE_B 49152
#define AH_O 0
#define AL_O 16384
#define BH_O 32768
#define DYN_BYTES (3 * STAGE_B + 1024)

#define SWZ(o) ((o) ^ (((o) >> 3) & 0x70))

// ---- device scratch --------------------------------------------------------
__device__ __half g_w1h[(size_t)NEXP * DHID * DIN];
__device__ __half g_w2h[(size_t)NEXP * DOUT * DHID];
__device__ __half g_xh[(size_t)BATCH * DIN];
__device__ __half g_xl[(size_t)BATCH * DIN];
__device__ __half g_hh[(size_t)MAX_ROWS * DHID];
__device__ __half g_hl[(size_t)MAX_ROWS * DHID];

__device__ int   g_tok_e[BATCH * 2];
__device__ float g_tok_p[BATCH * 2];
__device__ int   g_pair_token[MAX_ROWS];
__device__ float g_pair_w[MAX_ROWS];
__device__ int   g_offsets[NEXP + 1];

// ---- helpers ----------------------------------------------------------------
__device__ __forceinline__ uint32_t smem_u32(const void* p) {
    uint32_t a;
    asm("{ .reg .u64 t; cvta.to.shared.u64 t, %1; cvt.u32.u64 %0, t; }"
        : "=r"(a) : "l"(p));
    return a;
}
__device__ __forceinline__ void cp16(uint32_t s, const void* g) {
    asm volatile("cp.async.cg.shared.global [%0], [%1], 16;" :: "r"(s), "l"(g));
}
__device__ __forceinline__ void cp_commit() {
    asm volatile("cp.async.commit_group;" ::: "memory");
}
template <int N>
__device__ __forceinline__ void cp_wait() {
    asm volatile("cp.async.wait_group %0;" :: "n"(N) : "memory");
}
__device__ __forceinline__ void ldsm4(uint32_t* r, uint32_t addr) {
    asm volatile("ldmatrix.sync.aligned.m8n8.x4.shared.b16 {%0,%1,%2,%3}, [%4];"
                 : "=r"(r[0]), "=r"(r[1]), "=r"(r[2]), "=r"(r[3]) : "r"(addr));
}
__device__ __forceinline__ void mma16816(float* d, const uint32_t* a,
                                         const uint32_t* b) {
    asm volatile(
        "mma.sync.aligned.m16n8k16.row.col.f32.f16.f16.f32 "
        "{%0,%1,%2,%3}, {%4,%5,%6,%7}, {%8,%9}, {%0,%1,%2,%3};"
        : "+f"(d[0]), "+f"(d[1]), "+f"(d[2]), "+f"(d[3])
        : "r"(a[0]), "r"(a[1]), "r"(a[2]), "r"(a[3]), "r"(b[0]), "r"(b[1]));
}
// A-side split: a = hi + lo, both fp16 rn
__device__ __forceinline__ void splitA4(float4 v, uint32_t& hi0, uint32_t& hi1,
                                        uint32_t& lo0, uint32_t& lo1) {
    __half hx = __float2half_rn(v.x), hy = __float2half_rn(v.y);
    __half hz = __float2half_rn(v.z), hw = __float2half_rn(v.w);
    __half2 h0 = __halves2half2(hx, hy);
    __half2 h1 = __halves2half2(hz, hw);
    __half2 l0 = __floats2half2_rn(v.x - __half2float(hx), v.y - __half2float(hy));
    __half2 l1 = __floats2half2_rn(v.z - __half2float(hz), v.w - __half2float(hw));
    hi0 = *(uint32_t*)&h0;
    hi1 = *(uint32_t*)&h1;
    lo0 = *(uint32_t*)&l0;
    lo1 = *(uint32_t*)&l1;
}
__device__ __forceinline__ float geluf(float v) {
    return 0.5f * v * (1.0f + erff(v * 0.7071067811865476f));
}
__device__ __forceinline__ void store_splitA(__half* hh, __half* hl, size_t off,
                                             float v0, float v1) {
    __half h0 = __float2half_rn(v0), h1 = __float2half_rn(v1);
    __half2 hp = __halves2half2(h0, h1);
    __half2 lp = __floats2half2_rn(v0 - __half2float(h0), v1 - __half2float(h1));
    *(uint32_t*)(hh + off) = *(uint32_t*)&hp;
    *(uint32_t*)(hl + off) = *(uint32_t*)&lp;
}

// ---------------------------------------------------------------------------
__global__ void init_kernel(float* __restrict__ out, int out_n) {
    int stride = gridDim.x * blockDim.x;
    int i0 = blockIdx.x * blockDim.x + threadIdx.x;
    for (int i = i0; i < out_n; i += stride) out[i] = 0.0f;
    for (int i = i0; i < MAX_ROWS; i += stride) {
        g_pair_token[i] = 0;
        g_pair_w[i] = 0.0f;
    }
}

__global__ void gate_kernel(const float* __restrict__ x,
                            const float* __restrict__ gw) {
    int gtid = blockIdx.x * blockDim.x + threadIdx.x;
    int t = gtid >> 5;
    int lane = gtid & 31;
    if (t >= BATCH) return;
    const float* xr = x + (size_t)t * DIN;
    float acc[NEXP];
#pragma unroll
    for (int e = 0; e < NEXP; e++) acc[e] = 0.0f;
    for (int k = lane; k < DIN; k += 32) {
        float xv = __ldg(xr + k);
#pragma unroll
        for (int e = 0; e < NEXP; e++) acc[e] += xv * __ldg(gw + e * DIN + k);
    }
#pragma unroll
    for (int off = 16; off > 0; off >>= 1) {
#pragma unroll
        for (int e = 0; e < NEXP; e++)
            acc[e] += __shfl_xor_sync(0xffffffffu, acc[e], off);
    }
    if (lane == 0) {
        float v0 = -1e30f, v1 = -1e30f;
        int i0 = 0, i1 = 0;
#pragma unroll
        for (int e = 0; e < NEXP; e++) {
            float v = acc[e];
            if (v > v0) { v1 = v0; i1 = i0; v0 = v; i0 = e; }
            else if (v > v1) { v1 = v; i1 = e; }
        }
        float e1 = expf(v1 - v0);
        float s = 1.0f + e1;
        g_tok_e[2 * t + 0] = i0;
        g_tok_e[2 * t + 1] = i1;
        g_tok_p[2 * t + 0] = 1.0f / s;
        g_tok_p[2 * t + 1] = e1 / s;
    }
}

__global__ void offsets_kernel() {
    __shared__ int cnt[NEXP];
    if (threadIdx.x < NEXP) cnt[threadIdx.x] = 0;
    __syncthreads();
    for (int t = threadIdx.x; t < BATCH; t += blockDim.x) {
        atomicAdd(&cnt[g_tok_e[2 * t + 0]], 1);
        atomicAdd(&cnt[g_tok_e[2 * t + 1]], 1);
    }
    __syncthreads();
    if (threadIdx.x == 0) {
        int off = 0;
        for (int e = 0; e < NEXP; e++) {
            g_offsets[e] = off;
            off += ((cnt[e] + BM - 1) / BM) * BM;
        }
        g_offsets[NEXP] = off;
    }
}

__global__ void assign_kernel() {
    int e = blockIdx.x;
    __shared__ int wcnt[8];
    __shared__ int sbase;
    if (threadIdx.x == 0) sbase = g_offsets[e];
    __syncthreads();
    int base = sbase;
    int lane = threadIdx.x & 31;
    int wid = threadIdx.x >> 5;
    for (int t0 = 0; t0 < BATCH; t0 += 256) {
        int t = t0 + threadIdx.x;
        int sel = 0;
        float w = 0.0f;
        int e0 = g_tok_e[2 * t], e1 = g_tok_e[2 * t + 1];
        if (e0 == e)      { sel = 1; w = g_tok_p[2 * t]; }
        else if (e1 == e) { sel = 1; w = g_tok_p[2 * t + 1]; }
        unsigned m = __ballot_sync(0xffffffffu, sel);
        if (lane == 0) wcnt[wid] = __popc(m);
        __syncthreads();
        int prefix = 0, tot = 0;
#pragma unroll
        for (int i = 0; i < 8; i++) {
            if (i < wid) prefix += wcnt[i];
            tot += wcnt[i];
        }
        if (sel) {
            int pos = base + prefix + __popc(m & ((1u << lane) - 1u));
            g_pair_token[pos] = t;
            g_pair_w[pos] = w;
        }
        base += tot;
        __syncthreads();
    }
}

// x -> fp16 hi/lo split
__global__ void split_x(const float4* __restrict__ src, size_t n4) {
    uint2* hi = (uint2*)g_xh;
    uint2* lo = (uint2*)g_xl;
    size_t i = (size_t)blockIdx.x * blockDim.x + threadIdx.x;
    size_t stride = (size_t)gridDim.x * blockDim.x;
    for (; i < n4; i += stride) {
        float4 v = src[i];
        uint32_t h0, h1, l0, l1;
        splitA4(v, h0, h1, l0, l1);
        hi[i] = make_uint2(h0, h1);
        lo[i] = make_uint2(l0, l1);
    }
}

// weights -> single fp16 (which: 0=w1, 1=w2)
__global__ void conv_w(const float4* __restrict__ src, size_t n4, int which) {
    uint2* hi = (which == 0) ? (uint2*)g_w1h : (uint2*)g_w2h;
    size_t i = (size_t)blockIdx.x * blockDim.x + threadIdx.x;
    size_t stride = (size_t)gridDim.x * blockDim.x;
    for (; i < n4; i += stride) {
        float4 v = src[i];
        __half2 h0 = __floats2half2_rn(v.x, v.y);
        __half2 h1 = __floats2half2_rn(v.z, v.w);
        hi[i] = make_uint2(*(uint32_t*)&h0, *(uint32_t*)&h1);
    }
}

// ---------------------------------------------------------------------------
// Grouped GEMM: C[128x128] = A[128xK] * B[128xK]^T, fp16x2 asymmetric split.
// P1: A = x split (token gather), B = w1 fp16, epilogue gelu -> h split.
// P2: A = h split (direct rows),  B = w2 fp16, epilogue atomicAdd out.
// ---------------------------------------------------------------------------
template <int KDIM, bool P1>
__global__ void __launch_bounds__(256, 1)
mma_gemm(const float* __restrict__ bias, float* __restrict__ out) {
    const int mt = P1 ? blockIdx.x : blockIdx.y;
    const int nt = P1 ? blockIdx.y : blockIdx.x;
    __shared__ int s_off[NEXP + 1];
    __shared__ int stok[BM];
    __shared__ float ssw[BM];
    __shared__ float sbias[BN];
    extern __shared__ char dsm[];

    const int tid = threadIdx.x;
    if (tid < NEXP + 1) s_off[tid] = g_offsets[tid];
    __syncthreads();
    const int row0 = mt * BM;
    if (row0 >= s_off[NEXP]) return;
    int e = 0;
    while (row0 >= s_off[e + 1]) e++;
    if (tid < BM) {
        stok[tid] = g_pair_token[row0 + tid];
        ssw[tid] = g_pair_w[row0 + tid];
    }
    if (tid < BN)
        sbias[tid] = bias[(size_t)e * (P1 ? DHID : DOUT) + (size_t)nt * BN + tid];
    __syncthreads();

    const __half* Agh = P1 ? g_xh : g_hh;
    const __half* Agl = P1 ? g_xl : g_hl;
    const __half* Bgh = P1 ? g_w1h : g_w2h;

    uintptr_t pal = ((uintptr_t)dsm + 1023) & ~(uintptr_t)1023;
    const uint32_t su = smem_u32((void*)pal);

    // ---- cp.async producer mapping: thread -> 4 rows x 1 chunk per array ----
    const int ch = tid & 7;
    const int rb = tid >> 3;
    const __half* aH[4];
    const __half* aL[4];
    const __half* bH[4];
    uint32_t swz[4];
    const size_t brow0 = (size_t)e * (P1 ? DHID : DOUT) + (size_t)nt * BN;
#pragma unroll
    for (int i = 0; i < 4; i++) {
        int r = rb + i * 32;
        size_t ga = P1 ? (size_t)stok[r] * KDIM : (size_t)(row0 + r) * KDIM;
        aH[i] = Agh + ga + ch * 8;
        aL[i] = Agl + ga + ch * 8;
        size_t gb = (brow0 + r) * (size_t)KDIM;
        bH[i] = Bgh + gb + ch * 8;
        swz[i] = SWZ((uint32_t)r * 128 + (uint32_t)ch * 16);
    }

    auto issue = [&](int kt, int st) {
        uint32_t sb = su + st * STAGE_B;
        int ko = kt * 64;
#pragma unroll
        for (int i = 0; i < 4; i++) {
            cp16(sb + AH_O + swz[i], aH[i] + ko);
            cp16(sb + AL_O + swz[i], aL[i] + ko);
            cp16(sb + BH_O + swz[i], bH[i] + ko);
        }
    };

    issue(0, 0);
    cp_commit();
    issue(1, 1);
    cp_commit();

    // ---- consumer mapping ----
    const int wid = tid >> 5, lane = tid & 31;
    const int warp_m = (wid >> 1) * 32;
    const int warp_n = (wid & 1) * 64;
    const uint32_t xorv = (uint32_t)(lane & 7) << 4;
    const uint32_t kx = (uint32_t)((lane >> 4) << 4);
    const uint32_t rowA =
        (uint32_t)(warp_m + (lane & 7) + ((lane >> 3) & 1) * 8) * 128;
    const uint32_t rowB =
        (uint32_t)(warp_n + (lane & 7) + ((lane >> 3) & 1) * 8) * 128;

    float acc[2][8][4];
#pragma unroll
    for (int i = 0; i < 2; i++)
#pragma unroll
        for (int j = 0; j < 8; j++)
#pragma unroll
            for (int q = 0; q < 4; q++) acc[i][j][q] = 0.0f;

    const int NCH = KDIM / 64;
#pragma unroll 1
    for (int c = 0; c < NCH; c++) {
        cp_wait<1>();
        __syncthreads();
        if (c + 2 < NCH) issue(c + 2, (c + 2) % 3);
        cp_commit();
        const uint32_t sb = su + (c % 3) * STAGE_B;
#pragma unroll
        for (int s = 0; s < 4; s++) {
            const uint32_t kt = (((uint32_t)(s * 32)) + kx) ^ xorv;
            uint32_t ah[2][4], al[2][4], bh[4][4];
            ldsm4(ah[0], sb + AH_O + rowA + kt);
            ldsm4(ah[1], sb + AH_O + rowA + 2048 + kt);
            ldsm4(al[0], sb + AL_O + rowA + kt);
            ldsm4(al[1], sb + AL_O + rowA + 2048 + kt);
#pragma unroll
            for (int j = 0; j < 4; j++)
                ldsm4(bh[j], sb + BH_O + rowB + j * 2048 + kt);
#pragma unroll
            for (int mi = 0; mi < 2; mi++)
#pragma unroll
                for (int nj = 0; nj < 8; nj++) {
                    uint32_t bhi[2] = {bh[nj >> 1][nj & 1], bh[nj >> 1][(nj & 1) + 2]};
                    mma16816(acc[mi][nj], ah[mi], bhi);
                    mma16816(acc[mi][nj], al[mi], bhi);
                }
        }
    }

    // ---- epilogue ----
    const int g = lane >> 2, t4 = lane & 3;
    if (P1) {
#pragma unroll
        for (int mi = 0; mi < 2; mi++) {
            int r0 = warp_m + mi * 16 + g;
#pragma unroll
            for (int nj = 0; nj < 8; nj++) {
                int cB = warp_n + nj * 8 + 2 * t4;
                float b0v = sbias[cB], b1v = sbias[cB + 1];
                float v00 = geluf(acc[mi][nj][0] + b0v);
                float v01 = geluf(acc[mi][nj][1] + b1v);
                float v10 = geluf(acc[mi][nj][2] + b0v);
                float v11 = geluf(acc[mi][nj][3] + b1v);
                size_t gc = (size_t)nt * BN + cB;
                store_splitA(g_hh, g_hl, (size_t)(row0 + r0) * DHID + gc, v00, v01);
                store_splitA(g_hh, g_hl, (size_t)(row0 + r0 + 8) * DHID + gc, v10, v11);
            }
        }
    } else {
#pragma unroll
        for (int mi = 0; mi < 2; mi++) {
            int r0 = warp_m + mi * 16 + g;
            int tok0 = stok[r0], tok1 = stok[r0 + 8];
            float w0 = ssw[r0], w1 = ssw[r0 + 8];
            float* o0 = out + (size_t)tok0 * DOUT + (size_t)nt * BN;
            float* o1 = out + (size_t)tok1 * DOUT + (size_t)nt * BN;
#pragma unroll
            for (int nj = 0; nj < 8; nj++) {
                int cB = warp_n + nj * 8 + 2 * t4;
                float b0v = sbias[cB], b1v = sbias[cB + 1];
                atomicAdd(o0 + cB,     w0 * (acc[mi][nj][0] + b0v));
                atomicAdd(o0 + cB + 1, w0 * (acc[mi][nj][1] + b1v));
                atomicAdd(o1 + cB,     w1 * (acc[mi][nj][2] + b0v));
                atomicAdd(o1 + cB + 1, w1 * (acc[mi][nj][3] + b1v));
            }
        }
    }
}

// ---------------------------------------------------------------------------
extern "C" void kernel_launch(void* const* d_in, const int* in_sizes, int n_in,
                              void* d_out, int out_size) {
    const float* x  = (const float*)d_in[0];
    const float* gw = (const float*)d_in[1];
    const float* w1 = (const float*)d_in[2];
    const float* b1 = (const float*)d_in[3];
    const float* w2 = (const float*)d_in[4];
    const float* b2 = (const float*)d_in[5];
    float* out = (float*)d_out;

    cudaFuncSetAttribute(mma_gemm<DIN, true>,
                         cudaFuncAttributeMaxDynamicSharedMemorySize, DYN_BYTES);
    cudaFuncSetAttribute(mma_gemm<DHID, false>,
                         cudaFuncAttributeMaxDynamicSharedMemorySize, DYN_BYTES);

    init_kernel<<<2048, 256>>>(out, out_size);
    gate_kernel<<<(BATCH * 32 + 255) / 256, 256>>>(x, gw);
    offsets_kernel<<<1, 256>>>();
    assign_kernel<<<NEXP, 256>>>();

    size_t n4x = (size_t)BATCH * DIN / 4;
    size_t n4w1 = (size_t)NEXP * DHID * DIN / 4;
    size_t n4w2 = (size_t)NEXP * DOUT * DHID / 4;
    split_x<<<(int)((n4x + 255) / 256), 256>>>((const float4*)x, n4x);
    conv_w<<<65536, 256>>>((const float4*)w1, n4w1, 0);
    conv_w<<<65536, 256>>>((const float4*)w2, n4w2, 1);

    mma_gemm<DIN, true><<<dim3(NMT, DHID / BN), 256, DYN_BYTES>>>(b1, nullptr);
    mma_gemm<DHID, false><<<dim3(DOUT / BN, NMT), 256, DYN_BYTES>>>(b2, out);
}

// round 6
// speedup vs baseline: 7.1356x; 1.9999x over previous
#include <cuda_runtime.h>
#include <cuda_fp16.h>
#include <math.h>
#include <stdint.h>

// ---------------------------------------------------------------------------
// MoE top-2-of-8 via pure fp16 HMMA (fp32 accumulate).
// All GEMM operands rounded once to fp16 (rn). 4 independent incoherent
// rounding sources (x, w1, h, w2) ~2^-12 each -> rel_err ~4e-4 < 1e-3.
//  - pass1: h = gelu(x @ w1[e]^T + b1[e]) -> h fp16
//  - pass2: out += p * (h @ w2[e]^T + b2[e])  (fp32 atomicAdd)
// GEMM: 128x128 tiles, K-chunks of 64, cp.async 3-stage (96KB), 2 CTAs/SM.
// ---------------------------------------------------------------------------

#define BATCH 8192
#define NEXP  8
#define DIN   2048
#define DHID  8192
#define DOUT  2048

#define BM 128
#define BN 128
#define MAX_ROWS 17408
#define NMT (MAX_ROWS / BM)

#define STAGE_B 32768
#define A_O 0
#define B_O 16384
#define DYN_BYTES (3 * STAGE_B + 1024)

#define SWZ(o) ((o) ^ (((o) >> 3) & 0x70))

// ---- device scratch --------------------------------------------------------
__device__ __half g_w1h[(size_t)NEXP * DHID * DIN];
__device__ __half g_w2h[(size_t)NEXP * DOUT * DHID];
__device__ __half g_xh[(size_t)BATCH * DIN];
__device__ __half g_hh[(size_t)MAX_ROWS * DHID];

__device__ int   g_tok_e[BATCH * 2];
__device__ float g_tok_p[BATCH * 2];
__device__ int   g_pair_token[MAX_ROWS];
__device__ float g_pair_w[MAX_ROWS];
__device__ int   g_offsets[NEXP + 1];

// ---- helpers ----------------------------------------------------------------
__device__ __forceinline__ uint32_t smem_u32(const void* p) {
    uint32_t a;
    asm("{ .reg .u64 t; cvta.to.shared.u64 t, %1; cvt.u32.u64 %0, t; }"
        : "=r"(a) : "l"(p));
    return a;
}
__device__ __forceinline__ void cp16(uint32_t s, const void* g) {
    asm volatile("cp.async.cg.shared.global [%0], [%1], 16;" :: "r"(s), "l"(g));
}
__device__ __forceinline__ void cp_commit() {
    asm volatile("cp.async.commit_group;" ::: "memory");
}
template <int N>
__device__ __forceinline__ void cp_wait() {
    asm volatile("cp.async.wait_group %0;" :: "n"(N) : "memory");
}
__device__ __forceinline__ void ldsm4(uint32_t* r, uint32_t addr) {
    asm volatile("ldmatrix.sync.aligned.m8n8.x4.shared.b16 {%0,%1,%2,%3}, [%4];"
                 : "=r"(r[0]), "=r"(r[1]), "=r"(r[2]), "=r"(r[3]) : "r"(addr));
}
__device__ __forceinline__ void mma16816(float* d, const uint32_t* a,
                                         const uint32_t* b) {
    asm volatile(
        "mma.sync.aligned.m16n8k16.row.col.f32.f16.f16.f32 "
        "{%0,%1,%2,%3}, {%4,%5,%6,%7}, {%8,%9}, {%0,%1,%2,%3};"
        : "+f"(d[0]), "+f"(d[1]), "+f"(d[2]), "+f"(d[3])
        : "r"(a[0]), "r"(a[1]), "r"(a[2]), "r"(a[3]), "r"(b[0]), "r"(b[1]));
}
__device__ __forceinline__ float geluf(float v) {
    return 0.5f * v * (1.0f + erff(v * 0.7071067811865476f));
}

// ---------------------------------------------------------------------------
__global__ void init_kernel(float* __restrict__ out, int out_n) {
    int stride = gridDim.x * blockDim.x;
    int i0 = blockIdx.x * blockDim.x + threadIdx.x;
    for (int i = i0; i < out_n; i += stride) out[i] = 0.0f;
    for (int i = i0; i < MAX_ROWS; i += stride) {
        g_pair_token[i] = 0;
        g_pair_w[i] = 0.0f;
    }
}

__global__ void gate_kernel(const float* __restrict__ x,
                            const float* __restrict__ gw) {
    int gtid = blockIdx.x * blockDim.x + threadIdx.x;
    int t = gtid >> 5;
    int lane = gtid & 31;
    if (t >= BATCH) return;
    const float* xr = x + (size_t)t * DIN;
    float acc[NEXP];
#pragma unroll
    for (int e = 0; e < NEXP; e++) acc[e] = 0.0f;
    for (int k = lane; k < DIN; k += 32) {
        float xv = __ldg(xr + k);
#pragma unroll
        for (int e = 0; e < NEXP; e++) acc[e] += xv * __ldg(gw + e * DIN + k);
    }
#pragma unroll
    for (int off = 16; off > 0; off >>= 1) {
#pragma unroll
        for (int e = 0; e < NEXP; e++)
            acc[e] += __shfl_xor_sync(0xffffffffu, acc[e], off);
    }
    if (lane == 0) {
        float v0 = -1e30f, v1 = -1e30f;
        int i0 = 0, i1 = 0;
#pragma unroll
        for (int e = 0; e < NEXP; e++) {
            float v = acc[e];
            if (v > v0) { v1 = v0; i1 = i0; v0 = v; i0 = e; }
            else if (v > v1) { v1 = v; i1 = e; }
        }
        float e1 = expf(v1 - v0);
        float s = 1.0f + e1;
        g_tok_e[2 * t + 0] = i0;
        g_tok_e[2 * t + 1] = i1;
        g_tok_p[2 * t + 0] = 1.0f / s;
        g_tok_p[2 * t + 1] = e1 / s;
    }
}

__global__ void offsets_kernel() {
    __shared__ int cnt[NEXP];
    if (threadIdx.x < NEXP) cnt[threadIdx.x] = 0;
    __syncthreads();
    for (int t = threadIdx.x; t < BATCH; t += blockDim.x) {
        atomicAdd(&cnt[g_tok_e[2 * t + 0]], 1);
        atomicAdd(&cnt[g_tok_e[2 * t + 1]], 1);
    }
    __syncthreads();
    if (threadIdx.x == 0) {
        int off = 0;
        for (int e = 0; e < NEXP; e++) {
            g_offsets[e] = off;
            off += ((cnt[e] + BM - 1) / BM) * BM;
        }
        g_offsets[NEXP] = off;
    }
}

__global__ void assign_kernel() {
    int e = blockIdx.x;
    __shared__ int wcnt[8];
    __shared__ int sbase;
    if (threadIdx.x == 0) sbase = g_offsets[e];
    __syncthreads();
    int base = sbase;
    int lane = threadIdx.x & 31;
    int wid = threadIdx.x >> 5;
    for (int t0 = 0; t0 < BATCH; t0 += 256) {
        int t = t0 + threadIdx.x;
        int sel = 0;
        float w = 0.0f;
        int e0 = g_tok_e[2 * t], e1 = g_tok_e[2 * t + 1];
        if (e0 == e)      { sel = 1; w = g_tok_p[2 * t]; }
        else if (e1 == e) { sel = 1; w = g_tok_p[2 * t + 1]; }
        unsigned m = __ballot_sync(0xffffffffu, sel);
        if (lane == 0) wcnt[wid] = __popc(m);
        __syncthreads();
        int prefix = 0, tot = 0;
#pragma unroll
        for (int i = 0; i < 8; i++) {
            if (i < wid) prefix += wcnt[i];
            tot += wcnt[i];
        }
        if (sel) {
            int pos = base + prefix + __popc(m & ((1u << lane) - 1u));
            g_pair_token[pos] = t;
            g_pair_w[pos] = w;
        }
        base += tot;
        __syncthreads();
    }
}

// fp32 -> fp16 (which: 0=w1, 1=w2, 2=x)
__global__ void conv_h16(const float4* __restrict__ src, size_t n4, int which) {
    uint2* dst;
    if (which == 0)      dst = (uint2*)g_w1h;
    else if (which == 1) dst = (uint2*)g_w2h;
    else                 dst = (uint2*)g_xh;
    size_t i = (size_t)blockIdx.x * blockDim.x + threadIdx.x;
    size_t stride = (size_t)gridDim.x * blockDim.x;
    for (; i < n4; i += stride) {
        float4 v = src[i];
        __half2 h0 = __floats2half2_rn(v.x, v.y);
        __half2 h1 = __floats2half2_rn(v.z, v.w);
        dst[i] = make_uint2(*(uint32_t*)&h0, *(uint32_t*)&h1);
    }
}

// ---------------------------------------------------------------------------
// Grouped GEMM: C[128x128] = A[128xK] * B[128xK]^T, fp16 HMMA.
// P1: A = x fp16 (token gather), B = w1 fp16, epilogue gelu -> h fp16.
// P2: A = h fp16 (direct rows),  B = w2 fp16, epilogue atomicAdd out.
// ---------------------------------------------------------------------------
template <int KDIM, bool P1>
__global__ void __launch_bounds__(256, 2)
mma_gemm(const float* __restrict__ bias, float* __restrict__ out) {
    const int mt = P1 ? blockIdx.x : blockIdx.y;
    const int nt = P1 ? blockIdx.y : blockIdx.x;
    __shared__ int s_off[NEXP + 1];
    __shared__ int stok[BM];
    __shared__ float ssw[BM];
    __shared__ float sbias[BN];
    extern __shared__ char dsm[];

    const int tid = threadIdx.x;
    if (tid < NEXP + 1) s_off[tid] = g_offsets[tid];
    __syncthreads();
    const int row0 = mt * BM;
    if (row0 >= s_off[NEXP]) return;
    int e = 0;
    while (row0 >= s_off[e + 1]) e++;
    if (tid < BM) {
        stok[tid] = g_pair_token[row0 + tid];
        ssw[tid] = g_pair_w[row0 + tid];
    }
    if (tid < BN)
        sbias[tid] = bias[(size_t)e * (P1 ? DHID : DOUT) + (size_t)nt * BN + tid];
    __syncthreads();

    const __half* Ag = P1 ? g_xh : g_hh;
    const __half* Bg = P1 ? g_w1h : g_w2h;

    uintptr_t pal = ((uintptr_t)dsm + 1023) & ~(uintptr_t)1023;
    const uint32_t su = smem_u32((void*)pal);

    // ---- cp.async producer mapping: thread -> 4 rows x 1 chunk per array ----
    const int ch = tid & 7;
    const int rb = tid >> 3;
    const __half* aP[4];
    const __half* bP[4];
    uint32_t swz[4];
    const size_t brow0 = (size_t)e * (P1 ? DHID : DOUT) + (size_t)nt * BN;
#pragma unroll
    for (int i = 0; i < 4; i++) {
        int r = rb + i * 32;
        size_t ga = P1 ? (size_t)stok[r] * KDIM : (size_t)(row0 + r) * KDIM;
        aP[i] = Ag + ga + ch * 8;
        bP[i] = Bg + (brow0 + r) * (size_t)KDIM + ch * 8;
        swz[i] = SWZ((uint32_t)r * 128 + (uint32_t)ch * 16);
    }

    auto issue = [&](int kt, int st) {
        uint32_t sb = su + st * STAGE_B;
        int ko = kt * 64;
#pragma unroll
        for (int i = 0; i < 4; i++) {
            cp16(sb + A_O + swz[i], aP[i] + ko);
            cp16(sb + B_O + swz[i], bP[i] + ko);
        }
    };

    issue(0, 0);
    cp_commit();
    issue(1, 1);
    cp_commit();

    // ---- consumer mapping ----
    const int wid = tid >> 5, lane = tid & 31;
    const int warp_m = (wid >> 1) * 32;
    const int warp_n = (wid & 1) * 64;
    const uint32_t xorv = (uint32_t)(lane & 7) << 4;
    const uint32_t kx = (uint32_t)((lane >> 4) << 4);
    const uint32_t rowA =
        (uint32_t)(warp_m + (lane & 7) + ((lane >> 3) & 1) * 8) * 128;
    const uint32_t rowB =
        (uint32_t)(warp_n + (lane & 7) + ((lane >> 3) & 1) * 8) * 128;

    float acc[2][8][4];
#pragma unroll
    for (int i = 0; i < 2; i++)
#pragma unroll
        for (int j = 0; j < 8; j++)
#pragma unroll
            for (int q = 0; q < 4; q++) acc[i][j][q] = 0.0f;

    const int NCH = KDIM / 64;
#pragma unroll 1
    for (int c = 0; c < NCH; c++) {
        cp_wait<1>();
        __syncthreads();
        if (c + 2 < NCH) issue(c + 2, (c + 2) % 3);
        cp_commit();
        const uint32_t sb = su + (c % 3) * STAGE_B;
#pragma unroll
        for (int s = 0; s < 4; s++) {
            const uint32_t kt = (((uint32_t)(s * 32)) + kx) ^ xorv;
            uint32_t ah[2][4], bh[4][4];
            ldsm4(ah[0], sb + A_O + rowA + kt);
            ldsm4(ah[1], sb + A_O + rowA + 2048 + kt);
#pragma unroll
            for (int j = 0; j < 4; j++)
                ldsm4(bh[j], sb + B_O + rowB + j * 2048 + kt);
#pragma unroll
            for (int mi = 0; mi < 2; mi++)
#pragma unroll
                for (int nj = 0; nj < 8; nj++) {
                    uint32_t bhi[2] = {bh[nj >> 1][nj & 1], bh[nj >> 1][(nj & 1) + 2]};
                    mma16816(acc[mi][nj], ah[mi], bhi);
                }
        }
    }

    // ---- epilogue ----
    const int g = lane >> 2, t4 = lane & 3;
    if (P1) {
#pragma unroll
        for (int mi = 0; mi < 2; mi++) {
            int r0 = warp_m + mi * 16 + g;
#pragma unroll
            for (int nj = 0; nj < 8; nj++) {
                int cB = warp_n + nj * 8 + 2 * t4;
                float b0v = sbias[cB], b1v = sbias[cB + 1];
                float v00 = geluf(acc[mi][nj][0] + b0v);
                float v01 = geluf(acc[mi][nj][1] + b1v);
                float v10 = geluf(acc[mi][nj][2] + b0v);
                float v11 = geluf(acc[mi][nj][3] + b1v);
                size_t gc = (size_t)nt * BN + cB;
                __half2 p0 = __floats2half2_rn(v00, v01);
                __half2 p1 = __floats2half2_rn(v10, v11);
                *(uint32_t*)(g_hh + (size_t)(row0 + r0) * DHID + gc) =
                    *(uint32_t*)&p0;
                *(uint32_t*)(g_hh + (size_t)(row0 + r0 + 8) * DHID + gc) =
                    *(uint32_t*)&p1;
            }
        }
    } else {
#pragma unroll
        for (int mi = 0; mi < 2; mi++) {
            int r0 = warp_m + mi * 16 + g;
            int tok0 = stok[r0], tok1 = stok[r0 + 8];
            float w0 = ssw[r0], w1 = ssw[r0 + 8];
            float* o0 = out + (size_t)tok0 * DOUT + (size_t)nt * BN;
            float* o1 = out + (size_t)tok1 * DOUT + (size_t)nt * BN;
#pragma unroll
            for (int nj = 0; nj < 8; nj++) {
                int cB = warp_n + nj * 8 + 2 * t4;
                float b0v = sbias[cB], b1v = sbias[cB + 1];
                atomicAdd(o0 + cB,     w0 * (acc[mi][nj][0] + b0v));
                atomicAdd(o0 + cB + 1, w0 * (acc[mi][nj][1] + b1v));
                atomicAdd(o1 + cB,     w1 * (acc[mi][nj][2] + b0v));
                atomicAdd(o1 + cB + 1, w1 * (acc[mi][nj][3] + b1v));
            }
        }
    }
}

// ---------------------------------------------------------------------------
extern "C" void kernel_launch(void* const* d_in, const int* in_sizes, int n_in,
                              void* d_out, int out_size) {
    const float* x  = (const float*)d_in[0];
    const float* gw = (const float*)d_in[1];
    const float* w1 = (const float*)d_in[2];
    const float* b1 = (const float*)d_in[3];
    const float* w2 = (const float*)d_in[4];
    const float* b2 = (const float*)d_in[5];
    float* out = (float*)d_out;

    cudaFuncSetAttribute(mma_gemm<DIN, true>,
                         cudaFuncAttributeMaxDynamicSharedMemorySize, DYN_BYTES);
    cudaFuncSetAttribute(mma_gemm<DHID, false>,
                         cudaFuncAttributeMaxDynamicSharedMemorySize, DYN_BYTES);

    init_kernel<<<2048, 256>>>(out, out_size);
    gate_kernel<<<(BATCH * 32 + 255) / 256, 256>>>(x, gw);
    offsets_kernel<<<1, 256>>>();
    assign_kernel<<<NEXP, 256>>>();

    size_t n4x = (size_t)BATCH * DIN / 4;
    size_t n4w1 = (size_t)NEXP * DHID * DIN / 4;
    size_t n4w2 = (size_t)NEXP * DOUT * DHID / 4;
    conv_h16<<<(int)((n4x + 255) / 256), 256>>>((const float4*)x, n4x, 2);
    conv_h16<<<32768, 256>>>((const float4*)w1, n4w1, 0);
    conv_h16<<<32768, 256>>>((const float4*)w2, n4w2, 1);

    mma_gemm<DIN, true><<<dim3(NMT, DHID / BN), 256, DYN_BYTES>>>(b1, nullptr);
    mma_gemm<DHID, false><<<dim3(DOUT / BN, NMT), 256, DYN_BYTES>>>(b2, out);
}